// round 14
// baseline (speedup 1.0000x reference)
#include <cuda_runtime.h>
#include <cuda_fp16.h>
#include <cstdint>

#define THETA 0.7f
#define NB   32
#define NC   128
#define NH   128
#define NW   128
#define HWSZ (NH * NW)
#define IMG  (NC * HWSZ)
#define NTILES 2048
#define NCTA   148

// ---------------- scratch (static device memory; no allocation) -------------
// xTp: [b][hp=h+1 (0..129)][cc(2)] 16KB blocks, each [128 w][64 ci] fp16,
// SW128 swizzle baked into the byte layout.
static __device__ __align__(1024) unsigned char g_xTp[(size_t)32 * 130 * 2 * 16384];
// g_Uf: Winograd weights U = G g G^T in REGISTER-FRAGMENT layout:
// [cc(2)][p(16)][co_g(4)][mt(2)][ks(4)][lane(32)] x uint4 (16B). 512KB total.
// Within a uint4, component r: row+8 bit = r&1, k+8 bit = r>>1; the 2 halves
// of component r are ci bits: lane=(co&7)*4 | (ci>>1)&3, hi = ci&1.
static __device__ __align__(1024) unsigned char g_Uf[2 * 16 * 16384];
static __device__ float g_sp[2][NB * HWSZ];   // partial channel sums
static __device__ float g_d[NB * HWSZ];       // THETA * stencil

// ---------------- PTX helpers ----------------------------------------------
__device__ __forceinline__ uint32_t smem_u32(const void* p) {
    uint32_t a;
    asm("{ .reg .u64 t; cvta.to.shared.u64 t, %1; cvt.u32.u64 %0, t; }" : "=r"(a) : "l"(p));
    return a;
}
#define MBAR_INIT(a, n) asm volatile("mbarrier.init.shared.b64 [%0], %1;" :: "r"(a), "r"(n) : "memory")
#define MBAR_EXPECT_TX(a, b) asm volatile("mbarrier.arrive.expect_tx.shared.b64 _, [%0], %1;" :: "r"(a), "r"(b) : "memory")
__device__ __forceinline__ void mbar_wait(uint32_t mbar, uint32_t parity) {
    asm volatile(
        "{\n\t.reg .pred P;\n\t"
        "W_%=:\n\t"
        "mbarrier.try_wait.parity.acquire.cta.shared::cta.b64 P, [%0], %1, 0x989680;\n\t"
        "@!P bra W_%=;\n\t}" :: "r"(mbar), "r"(parity) : "memory");
}
__device__ __forceinline__ void bulk_g2s(uint32_t dst, const void* src, uint32_t bytes, uint32_t mbar) {
    asm volatile(
        "cp.async.bulk.shared::cta.global.mbarrier::complete_tx::bytes [%0], [%1], %2, [%3];"
        :: "r"(dst), "l"(src), "r"(bytes), "r"(mbar) : "memory");
}
__device__ __forceinline__ void ldsm4(uint32_t* r, uint32_t addr) {
    asm volatile("ldmatrix.sync.aligned.m8n8.x4.shared.b16 {%0,%1,%2,%3}, [%4];"
                 : "=r"(r[0]), "=r"(r[1]), "=r"(r[2]), "=r"(r[3]) : "r"(addr));
}
__device__ __forceinline__ void mma16816(float* c, const uint32_t* a, const uint32_t* b) {
    asm volatile(
        "mma.sync.aligned.m16n8k16.row.col.f32.f16.f16.f32 "
        "{%0,%1,%2,%3}, {%4,%5,%6,%7}, {%8,%9}, {%0,%1,%2,%3};"
        : "+f"(c[0]), "+f"(c[1]), "+f"(c[2]), "+f"(c[3])
        : "r"(a[0]), "r"(a[1]), "r"(a[2]), "r"(a[3]), "r"(b[0]), "r"(b[1]));
}
__device__ __forceinline__ uint32_t swz(uint32_t x) { return x ^ ((x >> 3) & 0x70); }

// ---------------- pre-pass kernels ------------------------------------------
__global__ void k_stencil() {
    int idx = blockIdx.x * blockDim.x + threadIdx.x;
    int b = idx >> 14, hw = idx & (HWSZ - 1);
    int h = hw >> 7, w = hw & 127;
    int base = b << 14;
    int hu = (h > 0   ? h - 1 : 0  ), hd = (h < 127 ? h + 1 : 127);
    int wl = (w > 0   ? w - 1 : 0  ), wr = (w < 127 ? w + 1 : 127);
    float c  = g_sp[0][base + hw]            + g_sp[1][base + hw];
    float up = g_sp[0][base + (hu << 7) + w] + g_sp[1][base + (hu << 7) + w];
    float dn = g_sp[0][base + (hd << 7) + w] + g_sp[1][base + (hd << 7) + w];
    float lf = g_sp[0][base + (h << 7) + wl] + g_sp[1][base + (h << 7) + wl];
    float rt = g_sp[0][base + (h << 7) + wr] + g_sp[1][base + (h << 7) + wr];
    g_d[idx] = THETA * (up + dn + lf + rt - 4.f * c);
}

// zero the pad rows hp=0 and hp=129 (2 blocks = 32KB per pad row per b)
__global__ void k_zero() {
    int i = blockIdx.x * blockDim.x + threadIdx.x;   // 131072 float4s total
    int b = i >> 12, rem = i & 4095;
    int pr = rem >> 11, j = rem & 2047;
    size_t off = ((size_t)(b * 130 + (pr ? 129 : 0))) * 32768 + (size_t)j * 16;
    *(float4*)(g_xTp + off) = make_float4(0.f, 0.f, 0.f, 0.f);
}

// Winograd weight transform into register-fragment layout (see g_Uf comment).
// G = [[1,0,0],[.5,.5,.5],[.5,-.5,.5],[0,0,1]]
__global__ void k_prep_u(const float* __restrict__ W) {
    int cc = blockIdx.x;
    for (int idx = threadIdx.x; idx < 8192; idx += 256) {
        int co = idx >> 6, ci = idx & 63;
        const float* gp = W + ((size_t)co * 128 + cc * 64 + ci) * 9;
        float g0[3][3];
#pragma unroll
        for (int kh = 0; kh < 3; ++kh)
#pragma unroll
            for (int kw = 0; kw < 3; ++kw) g0[kh][kw] = gp[kh * 3 + kw];
        float T[4][3];
#pragma unroll
        for (int c = 0; c < 3; ++c) {
            T[0][c] = g0[0][c];
            T[1][c] = 0.5f * (g0[0][c] + g0[1][c] + g0[2][c]);
            T[2][c] = 0.5f * (g0[0][c] - g0[1][c] + g0[2][c]);
            T[3][c] = g0[2][c];
        }
        float U4[4][4];
#pragma unroll
        for (int r = 0; r < 4; ++r) {
            U4[r][0] = T[r][0];
            U4[r][1] = 0.5f * (T[r][0] + T[r][1] + T[r][2]);
            U4[r][2] = 0.5f * (T[r][0] - T[r][1] + T[r][2]);
            U4[r][3] = T[r][2];
        }
        // fragment coordinates
        int lane = ((co & 7) << 2) | ((ci >> 1) & 3);
        int reg  = (((ci >> 3) & 1) << 1) | ((co >> 3) & 1);
        size_t base = (size_t)(co >> 5) * 4096 + (size_t)((co >> 4) & 1) * 2048
                    + (size_t)(ci >> 4) * 512 + (size_t)lane * 16
                    + (size_t)reg * 4 + (size_t)(ci & 1) * 2;
#pragma unroll
        for (int p = 0; p < 16; ++p)
            *(unsigned short*)(g_Uf + (size_t)(cc * 16 + p) * 16384 + base) =
                __half_as_ushort(__float2half(U4[p >> 2][p & 3]));
    }
}

// x: transpose [ci][w] -> [w][ci], fp16, bake swizzle, + partial chansum
__global__ void k_prep_x(const float* __restrict__ x) {
    extern __shared__ char ps[];
    float* xin = (float*)ps;                                  // [64][129]
    unsigned short* oh = (unsigned short*)(ps + 33024);       // 16KB
    int cc = blockIdx.x, h = blockIdx.y, b = blockIdx.z;
    const float* src = x + (size_t)b * IMG + ((size_t)cc * 64) * 16384 + (size_t)h * 128;
    for (int i = threadIdx.x; i < 8192; i += 256) {
        int ci = i >> 7, w = i & 127;
        xin[ci * 129 + w] = src[(size_t)ci * 16384 + w];
    }
    __syncthreads();
    if (threadIdx.x < 128) {
        int w = threadIdx.x;
        float s = 0.f;
#pragma unroll 16
        for (int ci = 0; ci < 64; ++ci) s += xin[ci * 129 + w];
        g_sp[cc][((size_t)b << 14) + ((size_t)h << 7) + w] = s;
    }
    for (int i = threadIdx.x; i < 8192; i += 256) {
        int w = i >> 6, ci = i & 63;
        uint32_t sw = swz((uint32_t)w * 128 + ci * 2);
        oh[sw >> 1] = __half_as_ushort(__float2half(xin[ci * 129 + w]));
    }
    __syncthreads();
    unsigned char* dst = g_xTp + ((size_t)((b * 130 + h + 1) * 2 + cc)) * 16384;
    float4* d0 = (float4*)dst;
    const float4* s0 = (const float4*)oh;
    for (int i = threadIdx.x; i < 1024; i += 256) d0[i] = s0[i];
}

// ---------------- main persistent Winograd mma.sync kernel -------------------
// 148 CTAs; CTA i handles tiles [i*2048/148, (i+1)*2048/148).
// Tile = one Winograd h-tile: output rows (h0,h0+1) x 128co x 128w.
// 512 threads, 16 warps: co_g = wid>>2 (32co), wt_g = wid&3 (16 w-tiles).
// Per cc-half: transform X->V in smem (2 syncs), then 16 GEMM stages with
// ZERO block-level syncs: U A-fragments come via __ldg from g_Uf (L2-hot),
// V B-fragments via verified ldsm path.
// SMEM: [8] xbar;
//       X: 2048  + 4*16384 = 65536   (rows h0-1..h0+2 of one cc)
//       V: 67584 + 16*8192 = 131072  -> total 198656
#define X_OFF 2048u
#define V_OFF 67584u
#define SMEM_TOTAL 198656

__global__ void __launch_bounds__(512) k_main(const float* __restrict__ bias,
                                              float* __restrict__ out) {
    extern __shared__ __align__(1024) char smem[];
    uint32_t sb = smem_u32(smem);
    const int tid = threadIdx.x, wid = tid >> 5, lane = tid & 31;
    const int co_g = wid >> 2;            // 0..3
    const int wt_g = wid & 3;             // 0..3

    const int start = (blockIdx.x * NTILES) / NCTA;
    const int end   = ((blockIdx.x + 1) * NTILES) / NCTA;

    if (tid == 0) {
        MBAR_INIT(sb + 8, 1);
        int b0 = start >> 6, h00 = (start & 63) * 2;
        const unsigned char* xp0 = g_xTp + (size_t)b0 * 130 * 32768;
        MBAR_EXPECT_TX(sb + 8, 65536u);
#pragma unroll
        for (int d = 0; d < 4; ++d)
            bulk_g2s(sb + X_OFF + (uint32_t)d * 16384u,
                     xp0 + (size_t)((h00 + d) * 2 + 0) * 16384, 16384u, sb + 8);
    }
    __syncthreads();

    // V-side ldsm coordinates (verified mapping)
    const int b_r = wt_g * 16 + (lane & 7) + ((lane >> 4) << 3);   // V row (wt)
    const uint32_t b_kb = (uint32_t)(((lane >> 3) & 1) << 4);
    const uint32_t b_xor = (uint32_t)((b_r & 7) << 4);
    // U-side fragment base (direct LDG)
    const unsigned char* ubase = g_Uf + (uint32_t)co_g * 4096u + (uint32_t)lane * 16u;

    // bias preload (4 co rows this thread touches)
    const int co0 = co_g * 32 + (lane >> 2);
    float bv[4];
    bv[0] = __ldg(&bias[co0]);      bv[1] = __ldg(&bias[co0 + 8]);
    bv[2] = __ldg(&bias[co0 + 16]); bv[3] = __ldg(&bias[co0 + 24]);

    float Y[2][2][16];
#pragma unroll
    for (int oy = 0; oy < 2; ++oy)
#pragma unroll
        for (int ox = 0; ox < 2; ++ox)
#pragma unroll
            for (int q = 0; q < 16; ++q) Y[oy][ox][q] = 0.f;

    int xev = 0;
    const __half2 hz = __float2half2_rn(0.f);

    for (int t = start; t < end; ++t) {
        const int b = t >> 6, h0 = (t & 63) * 2;
        const unsigned char* xp = g_xTp + (size_t)b * 130 * 32768;

#pragma unroll 1
        for (int cc = 0; cc < 2; ++cc) {
            // ---- input transform: X (4 rows) -> V (16 point blocks) --------
            mbar_wait(sb + 8, (uint32_t)(xev & 1)); ++xev;
#pragma unroll
            for (int it = 0; it < 4; ++it) {
                int el = tid + it * 512;          // 0..2047
                int wt = el >> 5, cp = el & 31;
                __half2 d[4][4];
#pragma unroll
                for (int c = 0; c < 4; ++c) {
                    int w = 2 * wt - 1 + c;
                    uint32_t byte = (uint32_t)(w & 127) * 128u + (uint32_t)cp * 4u;
                    uint32_t sw = byte ^ ((byte >> 3) & 0x70);
                    bool ok = (unsigned)w <= 127u;
#pragma unroll
                    for (int r = 0; r < 4; ++r)
                        d[r][c] = ok ? *(const __half2*)(smem + X_OFF + (uint32_t)r * 16384u + sw)
                                     : hz;
                }
                __half2 tv[4][4];
#pragma unroll
                for (int c = 0; c < 4; ++c) {
                    tv[0][c] = __hsub2(d[0][c], d[2][c]);
                    tv[1][c] = __hadd2(d[1][c], d[2][c]);
                    tv[2][c] = __hsub2(d[2][c], d[1][c]);
                    tv[3][c] = __hsub2(d[1][c], d[3][c]);
                }
                uint32_t sbyte = (uint32_t)wt * 128u + (uint32_t)cp * 4u;
                uint32_t ssw = sbyte ^ ((sbyte >> 3) & 0x70);
#pragma unroll
                for (int i = 0; i < 4; ++i) {
                    *(__half2*)(smem + V_OFF + (uint32_t)(i * 4 + 0) * 8192u + ssw) =
                        __hsub2(tv[i][0], tv[i][2]);
                    *(__half2*)(smem + V_OFF + (uint32_t)(i * 4 + 1) * 8192u + ssw) =
                        __hadd2(tv[i][1], tv[i][2]);
                    *(__half2*)(smem + V_OFF + (uint32_t)(i * 4 + 2) * 8192u + ssw) =
                        __hsub2(tv[i][2], tv[i][1]);
                    *(__half2*)(smem + V_OFF + (uint32_t)(i * 4 + 3) * 8192u + ssw) =
                        __hsub2(tv[i][1], tv[i][3]);
                }
            }
            __syncthreads();   // V visible; X reads done -> refill safe

            if (tid == 0) {
                if (cc == 0) {
                    MBAR_EXPECT_TX(sb + 8, 65536u);
#pragma unroll
                    for (int d2 = 0; d2 < 4; ++d2)
                        bulk_g2s(sb + X_OFF + (uint32_t)d2 * 16384u,
                                 xp + (size_t)((h0 + d2) * 2 + 1) * 16384, 16384u, sb + 8);
                } else if (t + 1 < end) {
                    int t1 = t + 1, b1 = t1 >> 6, h1 = (t1 & 63) * 2;
                    const unsigned char* xp1 = g_xTp + (size_t)b1 * 130 * 32768;
                    MBAR_EXPECT_TX(sb + 8, 65536u);
#pragma unroll
                    for (int d2 = 0; d2 < 4; ++d2)
                        bulk_g2s(sb + X_OFF + (uint32_t)d2 * 16384u,
                                 xp1 + (size_t)((h1 + d2) * 2 + 0) * 16384, 16384u, sb + 8);
                }
            }

            // ---- 16 GEMM stages, NO block syncs (U via LDG, V read-only) ---
            const unsigned char* ucc = ubase + (size_t)cc * 262144;
#pragma unroll 1
            for (int p = 0; p < 16; ++p) {
                const unsigned char* up = ucc + (uint32_t)p * 16384u;
                const uint32_t vb = sb + V_OFF + (uint32_t)p * 8192u
                                  + (uint32_t)b_r * 128u;
                float M[16];
#pragma unroll
                for (int q = 0; q < 16; ++q) M[q] = 0.f;

                uint4 au[2][2];
                au[0][0] = __ldg((const uint4*)(up));
                au[0][1] = __ldg((const uint4*)(up + 2048));
#pragma unroll
                for (int ks = 0; ks < 4; ++ks) {
                    if (ks < 3) {
                        au[(ks + 1) & 1][0] = __ldg((const uint4*)(up + (ks + 1) * 512));
                        au[(ks + 1) & 1][1] = __ldg((const uint4*)(up + 2048 + (ks + 1) * 512));
                    }
                    const uint32_t koB = ((uint32_t)(ks * 32) + b_kb) ^ b_xor;
                    uint32_t bh[4];
                    ldsm4(bh, vb + koB);
                    const uint32_t* a0 = (const uint32_t*)&au[ks & 1][0];
                    const uint32_t* a1 = (const uint32_t*)&au[ks & 1][1];
                    mma16816(&M[0],  a0, &bh[0]);
                    mma16816(&M[4],  a0, &bh[2]);
                    mma16816(&M[8],  a1, &bh[0]);
                    mma16816(&M[12], a1, &bh[2]);
                }
                // running output transform: Y += wy[i][oy]*wx[j][ox] * M
                {
                    const int i = p >> 2, j = p & 3;
                    const int wy0 = (i < 3) ? 1 : 0;
                    const int wy1 = (i == 0) ? 0 : ((i == 1) ? 1 : -1);
                    const int wx0 = (j < 3) ? 1 : 0;
                    const int wx1 = (j == 0) ? 0 : ((j == 1) ? 1 : -1);
#pragma unroll
                    for (int oy = 0; oy < 2; ++oy) {
                        const int wy = oy ? wy1 : wy0;
#pragma unroll
                        for (int ox = 0; ox < 2; ++ox) {
                            const int wgt = wy * (ox ? wx1 : wx0);
                            if (wgt == 1) {
#pragma unroll
                                for (int q = 0; q < 16; ++q) Y[oy][ox][q] += M[q];
                            } else if (wgt == -1) {
#pragma unroll
                                for (int q = 0; q < 16; ++q) Y[oy][ox][q] -= M[q];
                            }
                        }
                    }
                }
            }
            __syncthreads();   // V reads done before next transform overwrites
        }

        // ---- epilogue: direct register -> gmem, bias & stencil fused --------
#pragma unroll
        for (int oy = 0; oy < 2; ++oy) {
            const int h = h0 + oy;
            const float* gdr = g_d + ((size_t)b << 14) + ((size_t)h << 7);
            float* obr = out + (size_t)b * IMG + ((size_t)h << 7);
            float gdv[2][2][2];   // [ox][nt][kb]
#pragma unroll
            for (int ox = 0; ox < 2; ++ox)
#pragma unroll
                for (int nt = 0; nt < 2; ++nt)
#pragma unroll
                    for (int kb = 0; kb < 2; ++kb) {
                        int w = 2 * (wt_g * 16 + nt * 8 + ((lane & 3) << 1) + kb) + ox;
                        gdv[ox][nt][kb] = __ldg(&gdr[w]);
                    }
#pragma unroll
            for (int ox = 0; ox < 2; ++ox)
#pragma unroll
                for (int q = 0; q < 16; ++q) {
                    const int mt = q >> 3, nt = (q >> 2) & 1, k = q & 3;
                    const int co = co_g * 32 + mt * 16 + (lane >> 2) + ((k >> 1) << 3);
                    const int w  = 2 * (wt_g * 16 + nt * 8 + ((lane & 3) << 1) + (k & 1)) + ox;
                    obr[((size_t)co << 14) + w] =
                        Y[oy][ox][q] + bv[(mt << 1) | (k >> 1)] - gdv[ox][nt][k & 1];
                }
        }
#pragma unroll
        for (int oy = 0; oy < 2; ++oy)
#pragma unroll
            for (int ox = 0; ox < 2; ++ox)
#pragma unroll
                for (int q = 0; q < 16; ++q) Y[oy][ox][q] = 0.f;
    }
}

// ---------------------------------------------------------------------------
extern "C" void kernel_launch(void* const* d_in, const int* in_sizes, int n_in,
                              void* d_out, int out_size) {
    const float* x  = (const float*)d_in[0];
    const float* Wt = (const float*)d_in[1];
    const float* bb = (const float*)d_in[2];
    float* out = (float*)d_out;
    (void)in_sizes; (void)n_in; (void)out_size;

    cudaFuncSetAttribute(k_prep_x, cudaFuncAttributeMaxDynamicSharedMemorySize, 49408);
    cudaFuncSetAttribute(k_main,   cudaFuncAttributeMaxDynamicSharedMemorySize, SMEM_TOTAL);

    k_prep_u<<<2, 256>>>(Wt);
    k_zero<<<512, 256>>>();
    k_prep_x<<<dim3(2, 128, 32), 256, 49408>>>(x);
    k_stencil<<<NB * HWSZ / 256, 256>>>();
    k_main<<<NCTA, 512, SMEM_TOTAL>>>(bb, out);
}

// round 16
// speedup vs baseline: 1.3071x; 1.3071x over previous
#include <cuda_runtime.h>
#include <cuda_fp16.h>
#include <cstdint>

#define THETA 0.7f
#define NB   32
#define NC   128
#define NH   128
#define NW   128
#define HWSZ (NH * NW)
#define IMG  (NC * HWSZ)
#define NTILES 2048
#define NCTA   148

// ---------------- scratch (static device memory; no allocation) -------------
// xTp: [b][hp=h+1 (0..129)][cc(2)] 16KB blocks, each [128 w][64 ci] fp16,
// SW128 swizzle baked into the byte layout.
static __device__ __align__(1024) unsigned char g_xTp[(size_t)32 * 130 * 2 * 16384];
// Wp: 18 blocks ordered [(kh*2+cc)][kw], each 16KB [128 co][64 ci] fp16.
static __device__ __align__(1024) unsigned char g_Wp[18 * 16384];
static __device__ float g_sp[2][NB * HWSZ];   // partial channel sums
static __device__ float g_d[NB * HWSZ];       // THETA * stencil

// ---------------- PTX helpers ----------------------------------------------
__device__ __forceinline__ uint32_t smem_u32(const void* p) {
    uint32_t a;
    asm("{ .reg .u64 t; cvta.to.shared.u64 t, %1; cvt.u32.u64 %0, t; }" : "=r"(a) : "l"(p));
    return a;
}
#define MBAR_INIT(a, n) asm volatile("mbarrier.init.shared.b64 [%0], %1;" :: "r"(a), "r"(n) : "memory")
#define MBAR_EXPECT_TX(a, b) asm volatile("mbarrier.arrive.expect_tx.shared.b64 _, [%0], %1;" :: "r"(a), "r"(b) : "memory")
__device__ __forceinline__ void mbar_wait(uint32_t mbar, uint32_t parity) {
    asm volatile(
        "{\n\t.reg .pred P;\n\t"
        "W_%=:\n\t"
        "mbarrier.try_wait.parity.acquire.cta.shared::cta.b64 P, [%0], %1, 0x989680;\n\t"
        "@!P bra W_%=;\n\t}" :: "r"(mbar), "r"(parity) : "memory");
}
__device__ __forceinline__ void bulk_g2s(uint32_t dst, const void* src, uint32_t bytes, uint32_t mbar) {
    asm volatile(
        "cp.async.bulk.shared::cta.global.mbarrier::complete_tx::bytes [%0], [%1], %2, [%3];"
        :: "r"(dst), "l"(src), "r"(bytes), "r"(mbar) : "memory");
}
__device__ __forceinline__ void ldsm4(uint32_t* r, uint32_t addr) {
    asm volatile("ldmatrix.sync.aligned.m8n8.x4.shared.b16 {%0,%1,%2,%3}, [%4];"
                 : "=r"(r[0]), "=r"(r[1]), "=r"(r[2]), "=r"(r[3]) : "r"(addr));
}
// fp16-accumulator HMMA: D,C are 2 regs (4 packed halves), accumulate in place
__device__ __forceinline__ void mma16816h(uint32_t* c, const uint32_t* a, const uint32_t* b) {
    asm volatile(
        "mma.sync.aligned.m16n8k16.row.col.f16.f16.f16.f16 "
        "{%0,%1}, {%2,%3,%4,%5}, {%6,%7}, {%0,%1};"
        : "+r"(c[0]), "+r"(c[1])
        : "r"(a[0]), "r"(a[1]), "r"(a[2]), "r"(a[3]), "r"(b[0]), "r"(b[1]));
}
__device__ __forceinline__ uint32_t swz(uint32_t x) { return x ^ ((x >> 3) & 0x70); }

// ---------------- pre-pass kernels ------------------------------------------
__global__ void k_stencil() {
    int idx = blockIdx.x * blockDim.x + threadIdx.x;
    int b = idx >> 14, hw = idx & (HWSZ - 1);
    int h = hw >> 7, w = hw & 127;
    int base = b << 14;
    int hu = (h > 0   ? h - 1 : 0  ), hd = (h < 127 ? h + 1 : 127);
    int wl = (w > 0   ? w - 1 : 0  ), wr = (w < 127 ? w + 1 : 127);
    float c  = g_sp[0][base + hw]            + g_sp[1][base + hw];
    float up = g_sp[0][base + (hu << 7) + w] + g_sp[1][base + (hu << 7) + w];
    float dn = g_sp[0][base + (hd << 7) + w] + g_sp[1][base + (hd << 7) + w];
    float lf = g_sp[0][base + (h << 7) + wl] + g_sp[1][base + (h << 7) + wl];
    float rt = g_sp[0][base + (h << 7) + wr] + g_sp[1][base + (h << 7) + wr];
    g_d[idx] = THETA * (up + dn + lf + rt - 4.f * c);
}

// zero the pad rows hp=0 and hp=129 (2 blocks = 32KB per pad row per b)
__global__ void k_zero() {
    int i = blockIdx.x * blockDim.x + threadIdx.x;   // 131072 float4s total
    int b = i >> 12, rem = i & 4095;
    int pr = rem >> 11, j = rem & 2047;
    size_t off = ((size_t)(b * 130 + (pr ? 129 : 0))) * 32768 + (size_t)j * 16;
    *(float4*)(g_xTp + off) = make_float4(0.f, 0.f, 0.f, 0.f);
}

// weights: fp16 + SW128-bake; block index ((kh*2+cc)*3+kw)
__global__ void k_prep_w(const float* __restrict__ W) {
    int cc = blockIdx.x, kh = blockIdx.y, kw = blockIdx.z;
    size_t base = (size_t)((kh * 2 + cc) * 3 + kw) * 16384;
    for (int i = threadIdx.x; i < 8192; i += 256) {
        int co = i >> 6, ci = i & 63;
        float v = W[((size_t)co * 128 + cc * 64 + ci) * 9 + kh * 3 + kw];
        uint32_t sw = swz((uint32_t)co * 128 + ci * 2);
        *(unsigned short*)(g_Wp + base + sw) = __half_as_ushort(__float2half(v));
    }
}

// x: transpose [ci][w] -> [w][ci], fp16, bake swizzle, + partial chansum
__global__ void k_prep_x(const float* __restrict__ x) {
    extern __shared__ char ps[];
    float* xin = (float*)ps;                                  // [64][129]
    unsigned short* oh = (unsigned short*)(ps + 33024);       // 16KB
    int cc = blockIdx.x, h = blockIdx.y, b = blockIdx.z;
    const float* src = x + (size_t)b * IMG + ((size_t)cc * 64) * 16384 + (size_t)h * 128;
    for (int i = threadIdx.x; i < 8192; i += 256) {
        int ci = i >> 7, w = i & 127;
        xin[ci * 129 + w] = src[(size_t)ci * 16384 + w];
    }
    __syncthreads();
    if (threadIdx.x < 128) {
        int w = threadIdx.x;
        float s = 0.f;
#pragma unroll 16
        for (int ci = 0; ci < 64; ++ci) s += xin[ci * 129 + w];
        g_sp[cc][((size_t)b << 14) + ((size_t)h << 7) + w] = s;
    }
    for (int i = threadIdx.x; i < 8192; i += 256) {
        int w = i >> 6, ci = i & 63;
        uint32_t sw = swz((uint32_t)w * 128 + ci * 2);
        oh[sw >> 1] = __half_as_ushort(__float2half(xin[ci * 129 + w]));
    }
    __syncthreads();
    unsigned char* dst = g_xTp + ((size_t)((b * 130 + h + 1) * 2 + cc)) * 16384;
    float4* d0 = (float4*)dst;
    const float4* s0 = (const float4*)oh;
    for (int i = threadIdx.x; i < 1024; i += 256) d0[i] = s0[i];
}

// ---------------- main persistent mma.sync kernel (f16 accumulators) ---------
// 148 CTAs; CTA i handles tiles [i*2048/148, (i+1)*2048/148).
// Tile = 2 output rows (h0,h0+1) x 128co x 128w. 512 threads, 16 warps.
// warp: p = wid&1 (row), n_g = (wid>>1)&1 (64w half), co_g = wid>>2 (32co group)
// Stage s (0..5): kh = s>>1, cc = s&1. X ring slot = hp&3.
// Accumulators are packed f16 (Cf[16][2]) across all of K=1152; unpacked to
// f32 once in the epilogue. (Stencil term stays fp32 via g_d, so the f16
// rounding only touches the small conv component of the output.)
// SMEM: [8] xbar, [24],[32] wbar0/1; [64..192) zero row;
//       X ring: 2048 + 8*16384 = 133120  ([slot(4)][cc(2)] blocks)
//       W: 133120 + 2*49152 -> total 231424
#define X_OFF 2048u
#define W_OFF 133120u
#define SMEM_TOTAL 231424

__global__ void __launch_bounds__(512) k_main(const float* __restrict__ bias,
                                              float* __restrict__ out) {
    extern __shared__ __align__(1024) char smem[];
    uint32_t sb = smem_u32(smem);
    const int tid = threadIdx.x, wid = tid >> 5, lane = tid & 31;
    const int p    = wid & 1;
    const int n_g  = (wid >> 1) & 1;
    const int co_g = wid >> 2;            // 0..3
    const uint32_t zaddr = sb + 64;

    const int start = (blockIdx.x * NTILES) / NCTA;
    const int end   = ((blockIdx.x + 1) * NTILES) / NCTA;
    const int nstages = 6 * (end - start);

    if (tid == 0) { MBAR_INIT(sb + 8, 1); MBAR_INIT(sb + 24, 1); MBAR_INIT(sb + 32, 1); }
    if (tid < 32) ((float*)(smem + 64))[tid] = 0.f;

    // prologue: X rows hp=h0..h0+3 of first tile, W chunks 0 and 1
    {
        int b0 = start >> 6, h0 = (start & 63) * 2;
        const unsigned char* xp0 = g_xTp + (size_t)b0 * 130 * 32768;
        if (tid == 0) {
            MBAR_EXPECT_TX(sb + 8, 131072u);
#pragma unroll
            for (int d = 0; d < 4; ++d)
#pragma unroll
                for (int cc = 0; cc < 2; ++cc)
                    bulk_g2s(sb + X_OFF + (uint32_t)((((h0 + d) & 3) * 2 + cc)) * 16384u,
                             xp0 + (size_t)((h0 + d) * 2 + cc) * 16384, 16384u, sb + 8);
            MBAR_EXPECT_TX(sb + 24, 49152u);
            bulk_g2s(sb + W_OFF, g_Wp, 49152u, sb + 24);
            MBAR_EXPECT_TX(sb + 32, 49152u);
            bulk_g2s(sb + W_OFF + 49152u, g_Wp + 49152, 49152u, sb + 32);
        }
    }
    __syncthreads();   // zero-row + mbar init visible

    // ldmatrix per-thread coordinates (verified mapping)
    const int a_row = co_g * 32 + ((lane & 7) | (((lane >> 3) & 1) << 3));
    const uint32_t a_kb = (uint32_t)((lane >> 4) << 4);
    const int b_n  = (lane & 7) + ((lane >> 4) << 3) + n_g * 64;
    const uint32_t b_kb = (uint32_t)(((lane >> 3) & 1) << 4);
    const uint32_t a_xor = (uint32_t)((a_row & 7) << 4);

    const int row0 = co_g * 32 + (lane >> 2);
    const int col0 = n_g * 64 + 2 * (lane & 3);

    uint32_t Cf[16][2];   // packed f16 accumulators
#pragma unroll
    for (int nt = 0; nt < 16; ++nt) { Cf[nt][0] = 0u; Cf[nt][1] = 0u; }

    int g = 0;        // global W-stage counter
    int xev = 0;      // X arrival events consumed (parity = xev&1)

    for (int t = start; t < end; ++t) {
        const int b = t >> 6, h0 = (t & 63) * 2;
        const unsigned char* xp = g_xTp + (size_t)b * 130 * 32768;
        const bool fresh = (t == start) || ((t & 63) == 0);
        const bool next_exists = (t + 1 < end);
        const bool next_fresh  = next_exists && (((t + 1) & 63) == 0);
        const int wait_stage = fresh ? 0 : 2;

#pragma unroll 1
        for (int s = 0; s < 6; ++s) {
            const int kh = s >> 1, cc = s & 1;

            if (s == wait_stage) { mbar_wait(sb + 8, (uint32_t)(xev & 1)); ++xev; }
            mbar_wait(sb + 24u + (uint32_t)((g & 1) << 3), (uint32_t)(g >> 1) & 1u);

            const uint32_t wbuf = sb + W_OFF + (uint32_t)((g & 1) ? 49152u : 0u);
            const uint32_t xb = sb + X_OFF
                              + (uint32_t)((((h0 + p + kh) & 3) * 2 + cc)) * 16384u;

#pragma unroll
            for (int kw = 0; kw < 3; ++kw) {
                const uint32_t wkw = wbuf + (uint32_t)kw * 16384u
                                   + (uint32_t)a_row * 128u;
                uint32_t rh[4], rx[4];
#pragma unroll
                for (int ntp = 0; ntp < 4; ++ntp) {
                    int r = b_n + ntp * 16 + kw - 1;
                    if ((unsigned)r > 127u) { rh[ntp] = zaddr; rx[ntp] = 0u; }
                    else { rh[ntp] = xb + (uint32_t)r * 128u; rx[ntp] = (uint32_t)((r & 7) << 4); }
                }
#pragma unroll
                for (int ks = 0; ks < 4; ++ks) {
                    const uint32_t koA = (uint32_t)(ks * 32) + a_kb;
                    const uint32_t koB = (uint32_t)(ks * 32) + b_kb;
                    uint32_t ah0[4], ah1[4], bh[16];
                    ldsm4(ah0, wkw + (koA ^ a_xor));
                    ldsm4(ah1, wkw + 2048u + (koA ^ a_xor));   // +16 rows * 128B
#pragma unroll
                    for (int ntp = 0; ntp < 4; ++ntp)
                        ldsm4(&bh[ntp * 4], rh[ntp] + (koB ^ rx[ntp]));
#pragma unroll
                    for (int nt = 0; nt < 8; ++nt)
                        mma16816h(Cf[nt], ah0, &bh[((nt >> 1) << 2) + ((nt & 1) << 1)]);
#pragma unroll
                    for (int nt = 0; nt < 8; ++nt)
                        mma16816h(Cf[8 + nt], ah1, &bh[((nt >> 1) << 2) + ((nt & 1) << 1)]);
                }
            }

            __syncthreads();   // stage buffers fully consumed
            if (tid == 0) {
                if (g + 2 < nstages) {
                    uint32_t mb = sb + 24u + (uint32_t)((g & 1) << 3);
                    MBAR_EXPECT_TX(mb, 49152u);
                    bulk_g2s(sb + W_OFF + (uint32_t)((g & 1) ? 49152u : 0u),
                             g_Wp + (size_t)((g + 2) % 6) * 49152, 49152u, mb);
                }
                if (next_exists && !next_fresh && s == 3) {
                    // rows h0, h0+1 now dead; load next tile's rows h0+4, h0+5
                    MBAR_EXPECT_TX(sb + 8, 65536u);
#pragma unroll
                    for (int d = 4; d < 6; ++d)
#pragma unroll
                        for (int c2 = 0; c2 < 2; ++c2)
                            bulk_g2s(sb + X_OFF + (uint32_t)((((h0 + d) & 3) * 2 + c2)) * 16384u,
                                     xp + (size_t)((h0 + d) * 2 + c2) * 16384, 16384u, sb + 8);
                }
                if (next_fresh && s == 5) {
                    // full reload for column-crossing tile (h0'=0, new b)
                    int b1 = (t + 1) >> 6;
                    const unsigned char* xp1 = g_xTp + (size_t)b1 * 130 * 32768;
                    MBAR_EXPECT_TX(sb + 8, 131072u);
#pragma unroll
                    for (int d = 0; d < 4; ++d)
#pragma unroll
                        for (int c2 = 0; c2 < 2; ++c2)
                            bulk_g2s(sb + X_OFF + (uint32_t)(((d & 3) * 2 + c2)) * 16384u,
                                     xp1 + (size_t)(d * 2 + c2) * 16384, 16384u, sb + 8);
                }
            }
            ++g;
        }

        // ---- epilogue: unpack f16 -> f32, bias & stencil fused, direct gmem -
        {
            const float* gdp = g_d + ((size_t)b << 14) + ((size_t)(h0 + p) << 7);
            float* ob = out + (size_t)b * IMG + ((size_t)(h0 + p) << 7);
#pragma unroll
            for (int s16 = 0; s16 < 2; ++s16) {
                const int r0 = row0 + s16 * 16;
                const float bva = __ldg(&bias[r0]);
                const float bvb = __ldg(&bias[r0 + 8]);
                float* o0 = ob + ((size_t)r0 << 14);
                float* o1 = ob + ((size_t)(r0 + 8) << 14);
#pragma unroll
                for (int nt = 0; nt < 8; ++nt) {
                    const int c = col0 + nt * 8;
                    const float g0 = __ldg(&gdp[c]), g1 = __ldg(&gdp[c + 1]);
                    uint32_t* Cp = Cf[s16 * 8 + nt];
                    float2 f0 = __half22float2(*(__half2*)&Cp[0]);
                    float2 f1 = __half22float2(*(__half2*)&Cp[1]);
                    *(float2*)&o0[c] = make_float2(f0.x + bva - g0, f0.y + bva - g1);
                    *(float2*)&o1[c] = make_float2(f1.x + bvb - g0, f1.y + bvb - g1);
                }
            }
#pragma unroll
            for (int nt = 0; nt < 16; ++nt) { Cf[nt][0] = 0u; Cf[nt][1] = 0u; }
        }
    }
}

// ---------------------------------------------------------------------------
extern "C" void kernel_launch(void* const* d_in, const int* in_sizes, int n_in,
                              void* d_out, int out_size) {
    const float* x  = (const float*)d_in[0];
    const float* Wt = (const float*)d_in[1];
    const float* bb = (const float*)d_in[2];
    float* out = (float*)d_out;
    (void)in_sizes; (void)n_in; (void)out_size;

    cudaFuncSetAttribute(k_prep_x, cudaFuncAttributeMaxDynamicSharedMemorySize, 49408);
    cudaFuncSetAttribute(k_main,   cudaFuncAttributeMaxDynamicSharedMemorySize, SMEM_TOTAL);

    k_prep_w<<<dim3(2, 3, 3), 256>>>(Wt);
    k_zero<<<512, 256>>>();
    k_prep_x<<<dim3(2, 128, 32), 256, 49408>>>(x);
    k_stencil<<<NB * HWSZ / 256, 256>>>();
    k_main<<<NCTA, 512, SMEM_TOTAL>>>(bb, out);
}